// round 14
// baseline (speedup 1.0000x reference)
#include <cuda_runtime.h>
#include <cuda_fp16.h>
#include <math.h>
#include <stdint.h>

#define BB 8
#define NN 2048
#define CC 256
#define MM (BB*NN)   // 16384

// ---------------- scratch ----------------
__device__ float  g_H[MM*CC];       // h (row-major, exact fp32)
__device__ __half g_Hh[MM*CC];      // h fp16 (attention B operand)
__device__ float  g_feat[MM*CC];    // layer-2 input
__device__ float  g_el[2*MM];
__device__ float  g_er[2*MM];
__device__ __half g_elh[2*MM];
__device__ __half g_erh[2*MM];
__device__ __half g_Rh[2*MM];       // exp(er - ermax)
__device__ __half g_Sh[2*MM];       // exp(0.2(er - ermax))
__device__ __half g_Qh[2*MM];       // exp(-0.8*max(el+ermax,0))
__device__ __half g_Wh[4*256*128];  // W split hi (layer*2+head, k-major)
__device__ __half g_Wl[4*256*128];  // W split lo

// ---------------- helpers ----------------
__device__ __forceinline__ uint32_t smem_u32(const void* p) {
    uint32_t a;
    asm("{ .reg .u64 t; cvta.to.shared.u64 t, %1; cvt.u32.u64 %0, t; }" : "=r"(a) : "l"(p));
    return a;
}
__device__ __forceinline__ void cpa16(uint32_t d, const void* s) {
    asm volatile("cp.async.ca.shared.global [%0], [%1], 16;" :: "r"(d), "l"(s));
}
__device__ __forceinline__ void cpa16cg(uint32_t d, const void* s) {
    asm volatile("cp.async.cg.shared.global [%0], [%1], 16;" :: "r"(d), "l"(s));
}
#define CP_COMMIT() asm volatile("cp.async.commit_group;" ::: "memory")
#define CP_WAIT0()  asm volatile("cp.async.wait_group 0;" ::: "memory")
#define CP_WAIT1()  asm volatile("cp.async.wait_group 1;" ::: "memory")

__device__ __forceinline__ void mma16(float* c, const uint32_t* a,
                                      uint32_t b0, uint32_t b1) {
    asm volatile("mma.sync.aligned.m16n8k16.row.col.f32.f16.f16.f32 "
        "{%0,%1,%2,%3}, {%4,%5,%6,%7}, {%8,%9}, {%0,%1,%2,%3};"
        : "+f"(c[0]), "+f"(c[1]), "+f"(c[2]), "+f"(c[3])
        : "r"(a[0]), "r"(a[1]), "r"(a[2]), "r"(a[3]), "r"(b0), "r"(b1));
}
__device__ __forceinline__ void ldsm4t(uint32_t& r0, uint32_t& r1,
                                       uint32_t& r2, uint32_t& r3, uint32_t addr) {
    asm volatile("ldmatrix.sync.aligned.m8n8.x4.trans.shared.b16 {%0,%1,%2,%3}, [%4];"
        : "=r"(r0), "=r"(r1), "=r"(r2), "=r"(r3) : "r"(addr));
}

// fp16x2 weight pair: w = (el+er > 0) ? R : Q*S
__device__ __forceinline__ uint32_t wgt2(uint32_t el2, uint32_t q2, uint32_t er2,
                                         uint32_t r2, uint32_t s2) {
    __half2 t = __hadd2(*(__half2*)&el2, *(__half2*)&er2);
    uint32_t m = __hgt2_mask(t, __half2(__float2half_rn(0.f), __float2half_rn(0.f)));
    __half2 qs = __hmul2(*(__half2*)&q2, *(__half2*)&s2);
    uint32_t qsu = *(uint32_t*)&qs;
    return (r2 & m) | (qsu & ~m);
}

// ---------------------------------------------------------------------------
// K0: split all 4 W matrices into fp16 hi/lo, k-major. grid=512, block=256
// ---------------------------------------------------------------------------
__global__ __launch_bounds__(256) void wsplit_kernel(
    const float* __restrict__ W00, const float* __restrict__ W01,
    const float* __restrict__ W10, const float* __restrict__ W11)
{
    int i = blockIdx.x * 256 + threadIdx.x;     // 0..131071
    int m = i >> 15;
    const float* W = m == 0 ? W00 : m == 1 ? W01 : m == 2 ? W10 : W11;
    float w = W[i & 32767];
    __half hh = __float2half_rn(w);
    g_Wh[i] = hh;
    g_Wl[i] = __float2half_rn(w - __half2float(hh));
}

// ---------------------------------------------------------------------------
// K1: h = X @ W + b via fp16 2-term split (3 k16 mmas per k16 step).
// Fused el/er epilogue. grid = (M/128, 2), block = 256.
// ---------------------------------------------------------------------------
#define WROW 136

__global__ __launch_bounds__(256) void gemm_mma_kernel(
    const float* __restrict__ X,
    const float* __restrict__ a0_, const float* __restrict__ a1_,
    const float* __restrict__ b0_, const float* __restrict__ b1_,
    float* __restrict__ C, int layer)
{
    __shared__ float  Xs[128][36];
    __shared__ __half Whs[32][WROW];
    __shared__ __half Wls[32][WROW];
    __shared__ float  elp[128], erp[128];

    const int head = blockIdx.y;
    const float* __restrict__ bias = head ? b1_ : b0_;
    const float* __restrict__ av   = head ? a1_ : a0_;
    const __half* __restrict__ Wh = g_Wh + (size_t)(layer * 2 + head) * 32768;
    const __half* __restrict__ Wl = g_Wl + (size_t)(layer * 2 + head) * 32768;
    const int m0 = blockIdx.x * 128;

    const int t = threadIdx.x, warp = t >> 5, lane = t & 31;
    const int gid = lane >> 2, tig = lane & 3;
    const int Mg = warp >> 1, Ng = warp & 1;
    const int nb = Ng * 64;
    const int mm_ = lane >> 3, rsub = lane & 7;

    if (t < 128) { elp[t] = 0.f; erp[t] = 0.f; }

    const uint32_t lbh = smem_u32(&Whs[0][0])
        + (uint32_t)(((mm_ & 1) * 8 + rsub) * (WROW * 2) + ((mm_ >> 1) * 8 + nb) * 2);
    const uint32_t lbl = smem_u32(&Wls[0][0])
        + (uint32_t)(((mm_ & 1) * 8 + rsub) * (WROW * 2) + ((mm_ >> 1) * 8 + nb) * 2);

    float acc[2][8][4];
#pragma unroll
    for (int f = 0; f < 2; f++)
#pragma unroll
        for (int nt = 0; nt < 8; nt++)
#pragma unroll
            for (int c = 0; c < 4; c++) acc[f][nt][c] = 0.f;

    for (int k0 = 0; k0 < 256; k0 += 32) {
        __syncthreads();
#pragma unroll
        for (int q = 0; q < 2; q++) {
            int idx = q * 256 + t;
            int row = idx >> 4, seg = idx & 15;
            cpa16(smem_u32(&Whs[row][seg * 8]), Wh + (size_t)(k0 + row) * 128 + seg * 8);
            cpa16(smem_u32(&Wls[row][seg * 8]), Wl + (size_t)(k0 + row) * 128 + seg * 8);
        }
        CP_COMMIT();
#pragma unroll
        for (int q = 0; q < 4; q++) {
            int idx = q * 256 + t;
            int row = idx >> 3;
            int c4  = (idx & 7) * 4;
            *(float4*)&Xs[row][c4] =
                *(const float4*)(X + (size_t)(m0 + row) * CC + k0 + c4);
        }
        CP_WAIT0();
        __syncthreads();

#pragma unroll
        for (int ks = 0; ks < 2; ks++) {
            const int kb = ks * 16;
            uint32_t Ah[2][4], Al[2][4];
#pragma unroll
            for (int f = 0; f < 2; f++) {
                int r0 = Mg * 32 + f * 16 + gid;
#pragma unroll
                for (int q = 0; q < 4; q++) {
                    int row = r0 + (q & 1) * 8;
                    int kk  = kb + tig * 2 + (q >> 1) * 8;
                    float x0 = Xs[row][kk], x1 = Xs[row][kk + 1];
                    __half2 hi = __floats2half2_rn(x0, x1);
                    __half2 lo = __floats2half2_rn(x0 - __low2float(hi),
                                                   x1 - __high2float(hi));
                    Ah[f][q] = *(uint32_t*)&hi;
                    Al[f][q] = *(uint32_t*)&lo;
                }
            }
            const uint32_t kh = lbh + (uint32_t)ks * (16 * WROW * 2);
            const uint32_t kl = lbl + (uint32_t)ks * (16 * WROW * 2);
#pragma unroll
            for (int pnt = 0; pnt < 4; pnt++) {
                uint32_t bh0a, bh1a, bh0b, bh1b, bl0a, bl1a, bl0b, bl1b;
                ldsm4t(bh0a, bh1a, bh0b, bh1b, kh + pnt * 32);
                ldsm4t(bl0a, bl1a, bl0b, bl1b, kl + pnt * 32);
#pragma unroll
                for (int f = 0; f < 2; f++) {
                    mma16(acc[f][pnt * 2],     Ah[f], bl0a, bl1a);
                    mma16(acc[f][pnt * 2],     Al[f], bh0a, bh1a);
                    mma16(acc[f][pnt * 2],     Ah[f], bh0a, bh1a);
                    mma16(acc[f][pnt * 2 + 1], Ah[f], bl0b, bl1b);
                    mma16(acc[f][pnt * 2 + 1], Al[f], bh0b, bh1b);
                    mma16(acc[f][pnt * 2 + 1], Ah[f], bh0b, bh1b);
                }
            }
        }
    }

    // epilogue: bias, store C + Hh, fused el/er partials
    float elv[2][2] = {{0.f,0.f},{0.f,0.f}};
    float erv[2][2] = {{0.f,0.f},{0.f,0.f}};
#pragma unroll
    for (int f = 0; f < 2; f++) {
        int r0 = m0 + Mg * 32 + f * 16 + gid;
#pragma unroll
        for (int nt = 0; nt < 8; nt++) {
            int n = nb + nt * 8 + tig * 2;
            float2 bv  = *(const float2*)(bias + n);
            float2 al2 = *(const float2*)(av + n);
            float2 ar2 = *(const float2*)(av + 128 + n);
            float2 o0, o1;
            o0.x = acc[f][nt][0] + bv.x;
            o0.y = acc[f][nt][1] + bv.y;
            o1.x = acc[f][nt][2] + bv.x;
            o1.y = acc[f][nt][3] + bv.y;
            elv[f][0] += o0.x * al2.x + o0.y * al2.y;
            erv[f][0] += o0.x * ar2.x + o0.y * ar2.y;
            elv[f][1] += o1.x * al2.x + o1.y * al2.y;
            erv[f][1] += o1.x * ar2.x + o1.y * ar2.y;
            size_t off0 = (size_t)r0 * 256 + head * 128 + n;
            size_t off1 = (size_t)(r0 + 8) * 256 + head * 128 + n;
            *(float2*)(C + off0) = o0;
            *(float2*)(C + off1) = o1;
            *(__half2*)(g_Hh + off0) = __floats2half2_rn(o0.x, o0.y);
            *(__half2*)(g_Hh + off1) = __floats2half2_rn(o1.x, o1.y);
        }
    }
#pragma unroll
    for (int f = 0; f < 2; f++)
#pragma unroll
        for (int hh = 0; hh < 2; hh++) {
            elv[f][hh] += __shfl_xor_sync(0xFFFFFFFFu, elv[f][hh], 1);
            elv[f][hh] += __shfl_xor_sync(0xFFFFFFFFu, elv[f][hh], 2);
            erv[f][hh] += __shfl_xor_sync(0xFFFFFFFFu, erv[f][hh], 1);
            erv[f][hh] += __shfl_xor_sync(0xFFFFFFFFu, erv[f][hh], 2);
        }
    if (tig == 0) {
#pragma unroll
        for (int f = 0; f < 2; f++)
#pragma unroll
            for (int hh = 0; hh < 2; hh++) {
                int r = Mg * 32 + f * 16 + gid + hh * 8;
                atomicAdd(&elp[r], elv[f][hh]);
                atomicAdd(&erp[r], erv[f][hh]);
            }
    }
    __syncthreads();
    if (t < 128) {
        g_el[head * MM + m0 + t] = elp[t];
        g_er[head * MM + m0 + t] = erp[t];
    }
}

// ---------------------------------------------------------------------------
// K3: per (head,b): ermax, then fp16 R~/S~/Q + fp16 el/er
// ---------------------------------------------------------------------------
__global__ __launch_bounds__(256) void maxpqrs_kernel()
{
    int head = blockIdx.x >> 3;
    int b    = blockIdx.x & 7;
    int base = head * MM + b * NN;

    __shared__ float red[256];
    float m = -1e30f;
    for (int i = threadIdx.x; i < NN; i += 256) m = fmaxf(m, g_er[base + i]);
    red[threadIdx.x] = m;
    __syncthreads();
    for (int s = 128; s > 0; s >>= 1) {
        if (threadIdx.x < s) red[threadIdx.x] = fmaxf(red[threadIdx.x], red[threadIdx.x + s]);
        __syncthreads();
    }
    float ermax = red[0];

    for (int i = threadIdx.x; i < NN; i += 256) {
        float el = g_el[base + i];
        float er = g_er[base + i];
        float v  = el + ermax;
        g_elh[base + i] = __float2half(el);
        g_erh[base + i] = __float2half(er);
        g_Rh[base + i]  = __float2half(expf(er - ermax));
        g_Sh[base + i]  = __float2half(expf(0.2f * (er - ermax)));
        g_Qh[base + i]  = __float2half(v > 0.f ? expf(-0.8f * v) : 1.0f);
    }
}

// ---------------------------------------------------------------------------
// K4: attention via fp16 mma m16n8k16. Block = 128 threads (4 warps), CTA
// tile 64 i-rows x 64 cols; warp tile M=16 x N=64 -> ~85 regs/thread,
// grid = (64, 8, 2) = 1024 CTAs -> ~5 CTAs/SM. 32-j chunks, 3-stage pipeline.
// blockIdx.x = itile*2 + colhalf.
// ---------------------------------------------------------------------------
#define BROW 72                       // halfs per B smem row (64 + 8 pad)
#define BUFB (32*BROW*2)              // bytes per B buffer = 4608

__global__ __launch_bounds__(128, 5) void attn_mma_kernel(
    const float* __restrict__ H, float* __restrict__ Out)
{
    __shared__ __half Bs[3][32][BROW];
    __shared__ __half er_s[3][32], R_s[3][32], S_s[3][32];
    __shared__ __half elh_s[64], Qh_s[64];

    const int t = threadIdx.x, warp = t >> 5, lane = t & 31;
    const int gid = lane >> 2, tig = lane & 3;
    const int Mg = warp;                       // 4 warps = 4 M-groups of 16 rows
    const int colh = blockIdx.x & 1;
    const int nbg = colh * 64;                 // global col offset

    const int head = blockIdx.z, b = blockIdx.y, i0 = (blockIdx.x >> 1) * 64;
    const int rowbase = head * MM + b * NN;
    const float*  __restrict__ Hb  = H + (size_t)b * NN * CC + head * 128;
    const __half* __restrict__ Hbh = g_Hh + (size_t)b * NN * CC + head * 128;

    if (t < 64) {
        elh_s[t] = g_elh[rowbase + i0 + t];
        Qh_s[t]  = g_Qh[rowbase + i0 + t];
    }

    // ---- prologue: stage chunks 0 and 1 into buffers 0,1 ----
#pragma unroll
    for (int pc = 0; pc < 2; pc++) {
        const int j0 = pc * 32;
#pragma unroll
        for (int q = 0; q < 2; q++) {
            int idx = q * 128 + t;
            int row = idx >> 3;
            int seg = idx & 7;
            cpa16cg(smem_u32(&Bs[pc][row][seg * 8]),
                    Hbh + (size_t)(j0 + row) * CC + nbg + seg * 8);
        }
        if (t < 12) {
            int arr = t >> 2, q = t & 3;
            const __half* src = (arr == 0 ? g_erh : arr == 1 ? g_Rh : g_Sh)
                                + rowbase + j0 + q * 8;
            __half* dst = (arr == 0 ? er_s[pc] : arr == 1 ? R_s[pc] : S_s[pc]) + q * 8;
            cpa16(smem_u32(dst), src);
        }
        CP_COMMIT();
    }
    __syncthreads();

    // per-thread row constants as half2 broadcasts (2 rows: gid, gid+8)
    uint32_t el2[2], Q2[2];
#pragma unroll
    for (int hh = 0; hh < 2; hh++) {
        int r = Mg * 16 + gid + hh * 8;
        uint32_t e = (uint32_t)__half_as_ushort(elh_s[r]);
        uint32_t q = (uint32_t)__half_as_ushort(Qh_s[r]);
        el2[hh] = e * 0x00010001u;
        Q2[hh]  = q * 0x00010001u;
    }

    float acc[8][4];
    float zac[4];
#pragma unroll
    for (int c = 0; c < 4; c++) zac[c] = 0.f;
#pragma unroll
    for (int nt = 0; nt < 8; nt++)
#pragma unroll
        for (int c = 0; c < 4; c++) acc[nt][c] = 0.f;

    const int mm_ = lane >> 3, rsub = lane & 7;
    const uint32_t lbase = smem_u32(&Bs[0][0][0])
        + (uint32_t)(((mm_ & 1) * 8 + rsub) * (BROW * 2) + ((mm_ >> 1) * 8) * 2);

    const uint32_t ONES = 0x3C003C00u;

    int cur = 0;   // buffer index = ch % 3
    for (int ch = 0; ch < 64; ch++) {
        if (ch < 62) { CP_WAIT1(); } else { CP_WAIT0(); }
        __syncthreads();

        if (ch < 62) {
            int nx = cur + 2; if (nx >= 3) nx -= 3;
            const int j0 = (ch + 2) * 32;
#pragma unroll
            for (int q = 0; q < 2; q++) {
                int idx = q * 128 + t;
                int row = idx >> 3;
                int seg = idx & 7;
                cpa16cg(smem_u32(&Bs[nx][row][seg * 8]),
                        Hbh + (size_t)(j0 + row) * CC + nbg + seg * 8);
            }
            if (t < 12) {
                int arr = t >> 2, q = t & 3;
                const __half* src = (arr == 0 ? g_erh : arr == 1 ? g_Rh : g_Sh)
                                    + rowbase + j0 + q * 8;
                __half* dst = (arr == 0 ? er_s[nx] : arr == 1 ? R_s[nx] : S_s[nx]) + q * 8;
                cpa16(smem_u32(dst), src);
            }
            CP_COMMIT();
        }

        const uint32_t bbase = lbase + (uint32_t)cur * BUFB;

#pragma unroll
        for (int ks = 0; ks < 2; ks++) {
            const int jl = ks * 16 + tig * 2;
            uint32_t er2l = *(const uint32_t*)&er_s[cur][jl];
            uint32_t er2h = *(const uint32_t*)&er_s[cur][jl + 8];
            uint32_t R2l  = *(const uint32_t*)&R_s[cur][jl];
            uint32_t R2h  = *(const uint32_t*)&R_s[cur][jl + 8];
            uint32_t S2l  = *(const uint32_t*)&S_s[cur][jl];
            uint32_t S2h  = *(const uint32_t*)&S_s[cur][jl + 8];

            uint32_t A[4];
            A[0] = wgt2(el2[0], Q2[0], er2l, R2l, S2l);
            A[1] = wgt2(el2[1], Q2[1], er2l, R2l, S2l);
            A[2] = wgt2(el2[0], Q2[0], er2h, R2h, S2h);
            A[3] = wgt2(el2[1], Q2[1], er2h, R2h, S2h);

            mma16(zac, A, ONES, ONES);

            const uint32_t kaddr = bbase + (uint32_t)ks * (16 * BROW * 2);
#pragma unroll
            for (int pnt = 0; pnt < 4; pnt++) {
                uint32_t b0a, b1a, b0b, b1b;
                ldsm4t(b0a, b1a, b0b, b1b, kaddr + pnt * 32);
                mma16(acc[pnt * 2],     A, b0a, b1a);
                mma16(acc[pnt * 2 + 1], A, b0b, b1b);
            }
        }

        cur++; if (cur >= 3) cur = 0;
    }

    // epilogue: diag correction + identity + elu
    const __half h0 = __float2half_rn(0.f);
#pragma unroll
    for (int hh = 0; hh < 2; hh++) {
        int i  = i0 + Mg * 16 + gid + hh * 8;
        int gi = rowbase + i;
        float Z = zac[hh * 2];
        __half th = __hadd(g_elh[gi], g_erh[gi]);
        __half wh = __hgt(th, h0) ? g_Rh[gi] : __hmul(g_Qh[gi], g_Sh[gi]);
        float wii = __half2float(wh);
        float inv = 1.f / (Z - wii);
        const float* hi = Hb + (size_t)i * CC;
        float* op = Out + (size_t)(b * NN + i) * CC + head * 128;
#pragma unroll
        for (int nt = 0; nt < 8; nt++) {
            int col = nbg + nt * 8 + tig * 2;
            float2 hv = *(const float2*)(hi + col);
            float v0 = (acc[nt][hh * 2 + 0] - wii * hv.x) * inv + hv.x;
            float v1 = (acc[nt][hh * 2 + 1] - wii * hv.y) * inv + hv.y;
            float2 o;
            o.x = v0 > 0.f ? v0 : expm1f(v0);
            o.y = v1 > 0.f ? v1 : expm1f(v1);
            *(float2*)(op + col) = o;
        }
    }
}

// ---------------------------------------------------------------------------
extern "C" void kernel_launch(void* const* d_in, const int* in_sizes, int n_in,
                              void* d_out, int out_size)
{
    const float* x   = (const float*)d_in[0];
    const float* W00 = (const float*)d_in[2];
    const float* b00 = (const float*)d_in[3];
    const float* a00 = (const float*)d_in[4];
    const float* W01 = (const float*)d_in[5];
    const float* b01 = (const float*)d_in[6];
    const float* a01 = (const float*)d_in[7];
    const float* W10 = (const float*)d_in[8];
    const float* b10 = (const float*)d_in[9];
    const float* a10 = (const float*)d_in[10];
    const float* W11 = (const float*)d_in[11];
    const float* b11 = (const float*)d_in[12];
    const float* a11 = (const float*)d_in[13];
    float* out = (float*)d_out;

    float *H, *feat;
    cudaGetSymbolAddress((void**)&H,    g_H);
    cudaGetSymbolAddress((void**)&feat, g_feat);

    dim3 gemm_grid(MM / 128, 2);
    dim3 attn_grid(NN / 32, BB, 2);     // 64 x 8 x 2 = 1024 CTAs

    wsplit_kernel<<<512, 256>>>(W00, W01, W10, W11);

    // ---- Layer 1 ----
    gemm_mma_kernel<<<gemm_grid, 256>>>(x, a00, a01, b00, b01, H, 0);
    maxpqrs_kernel<<<16, 256>>>();
    attn_mma_kernel<<<attn_grid, 128>>>(H, feat);

    // ---- Layer 2 ----
    gemm_mma_kernel<<<gemm_grid, 256>>>(feat, a10, a11, b10, b11, H, 1);
    maxpqrs_kernel<<<16, 256>>>();
    attn_mma_kernel<<<attn_grid, 128>>>(H, out);
}

// round 17
// speedup vs baseline: 1.1099x; 1.1099x over previous
#include <cuda_runtime.h>
#include <cuda_fp16.h>
#include <math.h>
#include <stdint.h>

#define BB 8
#define NN 2048
#define CC 256
#define MM (BB*NN)   // 16384

// ---------------- scratch ----------------
__device__ float  g_H[MM*CC];       // h (row-major, exact fp32)
__device__ __half g_Hh[MM*CC];      // h fp16 (attention B operand)
__device__ float  g_feat[MM*CC];    // layer-2 input
__device__ float  g_el[2*MM];
__device__ float  g_er[2*MM];
__device__ __half g_Rh[2*MM];       // exp(er - ermax)
__device__ __half g_Sh[2*MM];       // exp(0.2(er - ermax))
__device__ __half g_Qh[2*MM];       // exp(-0.8*max(el+ermax,0))
__device__ __half g_Wh[4*256*128];  // W split hi (layer*2+head, k-major)
__device__ __half g_Wl[4*256*128];  // W split lo

// ---------------- helpers ----------------
__device__ __forceinline__ uint32_t smem_u32(const void* p) {
    uint32_t a;
    asm("{ .reg .u64 t; cvta.to.shared.u64 t, %1; cvt.u32.u64 %0, t; }" : "=r"(a) : "l"(p));
    return a;
}
__device__ __forceinline__ void cpa16(uint32_t d, const void* s) {
    asm volatile("cp.async.ca.shared.global [%0], [%1], 16;" :: "r"(d), "l"(s));
}
__device__ __forceinline__ void cpa16cg(uint32_t d, const void* s) {
    asm volatile("cp.async.cg.shared.global [%0], [%1], 16;" :: "r"(d), "l"(s));
}
#define CP_COMMIT() asm volatile("cp.async.commit_group;" ::: "memory")
#define CP_WAIT0()  asm volatile("cp.async.wait_group 0;" ::: "memory")
#define CP_WAIT1()  asm volatile("cp.async.wait_group 1;" ::: "memory")

__device__ __forceinline__ void mma16(float* c, const uint32_t* a,
                                      uint32_t b0, uint32_t b1) {
    asm volatile("mma.sync.aligned.m16n8k16.row.col.f32.f16.f16.f32 "
        "{%0,%1,%2,%3}, {%4,%5,%6,%7}, {%8,%9}, {%0,%1,%2,%3};"
        : "+f"(c[0]), "+f"(c[1]), "+f"(c[2]), "+f"(c[3])
        : "r"(a[0]), "r"(a[1]), "r"(a[2]), "r"(a[3]), "r"(b0), "r"(b1));
}
__device__ __forceinline__ void ldsm4t(uint32_t& r0, uint32_t& r1,
                                       uint32_t& r2, uint32_t& r3, uint32_t addr) {
    asm volatile("ldmatrix.sync.aligned.m8n8.x4.trans.shared.b16 {%0,%1,%2,%3}, [%4];"
        : "=r"(r0), "=r"(r1), "=r"(r2), "=r"(r3) : "r"(addr));
}

// fp16x2 weight pair: w = max(R, Q*S)   [exact: lrelu = max(t, 0.2t)]
__device__ __forceinline__ uint32_t wgt2(uint32_t q2, uint32_t r2, uint32_t s2) {
    __half2 qs = __hmul2(*(__half2*)&q2, *(__half2*)&s2);
    __half2 w  = __hmax2(*(__half2*)&r2, qs);
    return *(uint32_t*)&w;
}

// ---------------------------------------------------------------------------
// K0: split all 4 W matrices into fp16 hi/lo, k-major. grid=512, block=256
// ---------------------------------------------------------------------------
__global__ __launch_bounds__(256) void wsplit_kernel(
    const float* __restrict__ W00, const float* __restrict__ W01,
    const float* __restrict__ W10, const float* __restrict__ W11)
{
    int i = blockIdx.x * 256 + threadIdx.x;     // 0..131071
    int m = i >> 15;
    const float* W = m == 0 ? W00 : m == 1 ? W01 : m == 2 ? W10 : W11;
    float w = W[i & 32767];
    __half hh = __float2half_rn(w);
    g_Wh[i] = hh;
    g_Wl[i] = __float2half_rn(w - __half2float(hh));
}

// ---------------------------------------------------------------------------
// K1: h = X @ W + b via fp16 2-term split (3 k16 mmas per k16 step).
// Fused el/er epilogue. grid = (M/128, 2), block = 256.
// ---------------------------------------------------------------------------
#define WROW 136

__global__ __launch_bounds__(256) void gemm_mma_kernel(
    const float* __restrict__ X,
    const float* __restrict__ a0_, const float* __restrict__ a1_,
    const float* __restrict__ b0_, const float* __restrict__ b1_,
    float* __restrict__ C, int layer)
{
    __shared__ float  Xs[128][36];
    __shared__ __half Whs[32][WROW];
    __shared__ __half Wls[32][WROW];
    __shared__ float  elp[128], erp[128];

    const int head = blockIdx.y;
    const float* __restrict__ bias = head ? b1_ : b0_;
    const float* __restrict__ av   = head ? a1_ : a0_;
    const __half* __restrict__ Wh = g_Wh + (size_t)(layer * 2 + head) * 32768;
    const __half* __restrict__ Wl = g_Wl + (size_t)(layer * 2 + head) * 32768;
    const int m0 = blockIdx.x * 128;

    const int t = threadIdx.x, warp = t >> 5, lane = t & 31;
    const int gid = lane >> 2, tig = lane & 3;
    const int Mg = warp >> 1, Ng = warp & 1;
    const int nb = Ng * 64;
    const int mm_ = lane >> 3, rsub = lane & 7;

    if (t < 128) { elp[t] = 0.f; erp[t] = 0.f; }

    const uint32_t lbh = smem_u32(&Whs[0][0])
        + (uint32_t)(((mm_ & 1) * 8 + rsub) * (WROW * 2) + ((mm_ >> 1) * 8 + nb) * 2);
    const uint32_t lbl = smem_u32(&Wls[0][0])
        + (uint32_t)(((mm_ & 1) * 8 + rsub) * (WROW * 2) + ((mm_ >> 1) * 8 + nb) * 2);

    float acc[2][8][4];
#pragma unroll
    for (int f = 0; f < 2; f++)
#pragma unroll
        for (int nt = 0; nt < 8; nt++)
#pragma unroll
            for (int c = 0; c < 4; c++) acc[f][nt][c] = 0.f;

    for (int k0 = 0; k0 < 256; k0 += 32) {
        __syncthreads();
#pragma unroll
        for (int q = 0; q < 2; q++) {
            int idx = q * 256 + t;
            int row = idx >> 4, seg = idx & 15;
            cpa16(smem_u32(&Whs[row][seg * 8]), Wh + (size_t)(k0 + row) * 128 + seg * 8);
            cpa16(smem_u32(&Wls[row][seg * 8]), Wl + (size_t)(k0 + row) * 128 + seg * 8);
        }
        CP_COMMIT();
#pragma unroll
        for (int q = 0; q < 4; q++) {
            int idx = q * 256 + t;
            int row = idx >> 3;
            int c4  = (idx & 7) * 4;
            *(float4*)&Xs[row][c4] =
                *(const float4*)(X + (size_t)(m0 + row) * CC + k0 + c4);
        }
        CP_WAIT0();
        __syncthreads();

#pragma unroll
        for (int ks = 0; ks < 2; ks++) {
            const int kb = ks * 16;
            uint32_t Ah[2][4], Al[2][4];
#pragma unroll
            for (int f = 0; f < 2; f++) {
                int r0 = Mg * 32 + f * 16 + gid;
#pragma unroll
                for (int q = 0; q < 4; q++) {
                    int row = r0 + (q & 1) * 8;
                    int kk  = kb + tig * 2 + (q >> 1) * 8;
                    float x0 = Xs[row][kk], x1 = Xs[row][kk + 1];
                    __half2 hi = __floats2half2_rn(x0, x1);
                    __half2 lo = __floats2half2_rn(x0 - __low2float(hi),
                                                   x1 - __high2float(hi));
                    Ah[f][q] = *(uint32_t*)&hi;
                    Al[f][q] = *(uint32_t*)&lo;
                }
            }
            const uint32_t kh = lbh + (uint32_t)ks * (16 * WROW * 2);
            const uint32_t kl = lbl + (uint32_t)ks * (16 * WROW * 2);
#pragma unroll
            for (int pnt = 0; pnt < 4; pnt++) {
                uint32_t bh0a, bh1a, bh0b, bh1b, bl0a, bl1a, bl0b, bl1b;
                ldsm4t(bh0a, bh1a, bh0b, bh1b, kh + pnt * 32);
                ldsm4t(bl0a, bl1a, bl0b, bl1b, kl + pnt * 32);
#pragma unroll
                for (int f = 0; f < 2; f++) {
                    mma16(acc[f][pnt * 2],     Ah[f], bl0a, bl1a);
                    mma16(acc[f][pnt * 2],     Al[f], bh0a, bh1a);
                    mma16(acc[f][pnt * 2],     Ah[f], bh0a, bh1a);
                    mma16(acc[f][pnt * 2 + 1], Ah[f], bl0b, bl1b);
                    mma16(acc[f][pnt * 2 + 1], Al[f], bh0b, bh1b);
                    mma16(acc[f][pnt * 2 + 1], Ah[f], bh0b, bh1b);
                }
            }
        }
    }

    // epilogue: bias, store C + Hh, fused el/er partials
    float elv[2][2] = {{0.f,0.f},{0.f,0.f}};
    float erv[2][2] = {{0.f,0.f},{0.f,0.f}};
#pragma unroll
    for (int f = 0; f < 2; f++) {
        int r0 = m0 + Mg * 32 + f * 16 + gid;
#pragma unroll
        for (int nt = 0; nt < 8; nt++) {
            int n = nb + nt * 8 + tig * 2;
            float2 bv  = *(const float2*)(bias + n);
            float2 al2 = *(const float2*)(av + n);
            float2 ar2 = *(const float2*)(av + 128 + n);
            float2 o0, o1;
            o0.x = acc[f][nt][0] + bv.x;
            o0.y = acc[f][nt][1] + bv.y;
            o1.x = acc[f][nt][2] + bv.x;
            o1.y = acc[f][nt][3] + bv.y;
            elv[f][0] += o0.x * al2.x + o0.y * al2.y;
            erv[f][0] += o0.x * ar2.x + o0.y * ar2.y;
            elv[f][1] += o1.x * al2.x + o1.y * al2.y;
            erv[f][1] += o1.x * ar2.x + o1.y * ar2.y;
            size_t off0 = (size_t)r0 * 256 + head * 128 + n;
            size_t off1 = (size_t)(r0 + 8) * 256 + head * 128 + n;
            *(float2*)(C + off0) = o0;
            *(float2*)(C + off1) = o1;
            *(__half2*)(g_Hh + off0) = __floats2half2_rn(o0.x, o0.y);
            *(__half2*)(g_Hh + off1) = __floats2half2_rn(o1.x, o1.y);
        }
    }
#pragma unroll
    for (int f = 0; f < 2; f++)
#pragma unroll
        for (int hh = 0; hh < 2; hh++) {
            elv[f][hh] += __shfl_xor_sync(0xFFFFFFFFu, elv[f][hh], 1);
            elv[f][hh] += __shfl_xor_sync(0xFFFFFFFFu, elv[f][hh], 2);
            erv[f][hh] += __shfl_xor_sync(0xFFFFFFFFu, erv[f][hh], 1);
            erv[f][hh] += __shfl_xor_sync(0xFFFFFFFFu, erv[f][hh], 2);
        }
    if (tig == 0) {
#pragma unroll
        for (int f = 0; f < 2; f++)
#pragma unroll
            for (int hh = 0; hh < 2; hh++) {
                int r = Mg * 32 + f * 16 + gid + hh * 8;
                atomicAdd(&elp[r], elv[f][hh]);
                atomicAdd(&erp[r], erv[f][hh]);
            }
    }
    __syncthreads();
    if (t < 128) {
        g_el[head * MM + m0 + t] = elp[t];
        g_er[head * MM + m0 + t] = erp[t];
    }
}

// ---------------------------------------------------------------------------
// K3: per (head,b): ermax, then fp16 R~/S~/Q
// ---------------------------------------------------------------------------
__global__ __launch_bounds__(256) void maxpqrs_kernel()
{
    int head = blockIdx.x >> 3;
    int b    = blockIdx.x & 7;
    int base = head * MM + b * NN;

    __shared__ float red[256];
    float m = -1e30f;
    for (int i = threadIdx.x; i < NN; i += 256) m = fmaxf(m, g_er[base + i]);
    red[threadIdx.x] = m;
    __syncthreads();
    for (int s = 128; s > 0; s >>= 1) {
        if (threadIdx.x < s) red[threadIdx.x] = fmaxf(red[threadIdx.x], red[threadIdx.x + s]);
        __syncthreads();
    }
    float ermax = red[0];

    for (int i = threadIdx.x; i < NN; i += 256) {
        float el = g_el[base + i];
        float er = g_er[base + i];
        float v  = el + ermax;
        g_Rh[base + i] = __float2half(expf(er - ermax));
        g_Sh[base + i] = __float2half(expf(0.2f * (er - ermax)));
        g_Qh[base + i] = __float2half(v > 0.f ? expf(-0.8f * v) : 1.0f);
    }
}

// ---------------------------------------------------------------------------
// K4: attention via fp16 mma m16n8k16. Block = 128 threads (4 warps), CTA
// tile 128 i-rows x 64 cols -> 4 CTAs/SM. Warp tile M=32 x N=64.
// Weights: w = max(R_j, Q_i*S_j)  (2 instrs per half2 pair).
// 32-j chunks, 3-stage cp.async pipeline.
// grid = (32, 8, 2): blockIdx.x = itile*2 + colhalf. block = 128.
// ---------------------------------------------------------------------------
#define BROW 72                       // halfs per B smem row (64 + 8 pad)
#define BUFB (32*BROW*2)              // bytes per B buffer = 4608

__global__ __launch_bounds__(128, 4) void attn_mma_kernel(
    const float* __restrict__ H, float* __restrict__ Out)
{
    __shared__ __half Bs[3][32][BROW];
    __shared__ __half R_s[3][32], S_s[3][32];
    __shared__ __half Qh_s[128];

    const int t = threadIdx.x, warp = t >> 5, lane = t & 31;
    const int gid = lane >> 2, tig = lane & 3;
    const int Mg = warp;                       // 4 warps = 4 M-groups of 32
    const int colh = blockIdx.x & 1;
    const int nbg = colh * 64;                 // global col offset

    const int head = blockIdx.z, b = blockIdx.y, i0 = (blockIdx.x >> 1) * 128;
    const int rowbase = head * MM + b * NN;
    const float*  __restrict__ Hb  = H + (size_t)b * NN * CC + head * 128;
    const __half* __restrict__ Hbh = g_Hh + (size_t)b * NN * CC + head * 128;

    Qh_s[t] = g_Qh[rowbase + i0 + t];

    // ---- prologue: stage chunks 0 and 1 into buffers 0,1 ----
#pragma unroll
    for (int pc = 0; pc < 2; pc++) {
        const int j0 = pc * 32;
#pragma unroll
        for (int q = 0; q < 2; q++) {
            int idx = q * 128 + t;
            int row = idx >> 3;
            int seg = idx & 7;
            cpa16cg(smem_u32(&Bs[pc][row][seg * 8]),
                    Hbh + (size_t)(j0 + row) * CC + nbg + seg * 8);
        }
        if (t < 8) {
            int arr = t >> 2, q = t & 3;
            const __half* src = (arr == 0 ? g_Rh : g_Sh) + rowbase + j0 + q * 8;
            __half* dst = (arr == 0 ? R_s[pc] : S_s[pc]) + q * 8;
            cpa16(smem_u32(dst), src);
        }
        CP_COMMIT();
    }
    __syncthreads();

    // per-thread row constants as half2 broadcasts (4 rows: 2 frags x {low,high})
    uint32_t Q2[2][2];
#pragma unroll
    for (int f = 0; f < 2; f++)
#pragma unroll
        for (int hh = 0; hh < 2; hh++) {
            int r = Mg * 32 + f * 16 + gid + hh * 8;
            Q2[f][hh] = (uint32_t)__half_as_ushort(Qh_s[r]) * 0x00010001u;
        }

    float acc[2][8][4];
    float zac[2][4];
#pragma unroll
    for (int f = 0; f < 2; f++) {
#pragma unroll
        for (int c = 0; c < 4; c++) zac[f][c] = 0.f;
#pragma unroll
        for (int nt = 0; nt < 8; nt++)
#pragma unroll
            for (int c = 0; c < 4; c++) acc[f][nt][c] = 0.f;
    }

    const int mm_ = lane >> 3, rsub = lane & 7;
    const uint32_t lbase = smem_u32(&Bs[0][0][0])
        + (uint32_t)(((mm_ & 1) * 8 + rsub) * (BROW * 2) + ((mm_ >> 1) * 8) * 2);

    const uint32_t ONES = 0x3C003C00u;

    int cur = 0;   // buffer index = ch % 3
    for (int ch = 0; ch < 64; ch++) {
        if (ch < 62) { CP_WAIT1(); } else { CP_WAIT0(); }
        __syncthreads();

        if (ch < 62) {
            int nx = cur + 2; if (nx >= 3) nx -= 3;
            const int j0 = (ch + 2) * 32;
#pragma unroll
            for (int q = 0; q < 2; q++) {
                int idx = q * 128 + t;
                int row = idx >> 3;
                int seg = idx & 7;
                cpa16cg(smem_u32(&Bs[nx][row][seg * 8]),
                        Hbh + (size_t)(j0 + row) * CC + nbg + seg * 8);
            }
            if (t < 8) {
                int arr = t >> 2, q = t & 3;
                const __half* src = (arr == 0 ? g_Rh : g_Sh) + rowbase + j0 + q * 8;
                __half* dst = (arr == 0 ? R_s[nx] : S_s[nx]) + q * 8;
                cpa16(smem_u32(dst), src);
            }
            CP_COMMIT();
        }

        const uint32_t bbase = lbase + (uint32_t)cur * BUFB;

#pragma unroll
        for (int ks = 0; ks < 2; ks++) {
            const int jl = ks * 16 + tig * 2;
            uint32_t R2l = *(const uint32_t*)&R_s[cur][jl];
            uint32_t R2h = *(const uint32_t*)&R_s[cur][jl + 8];
            uint32_t S2l = *(const uint32_t*)&S_s[cur][jl];
            uint32_t S2h = *(const uint32_t*)&S_s[cur][jl + 8];

            uint32_t A[2][4];
#pragma unroll
            for (int f = 0; f < 2; f++) {
                A[f][0] = wgt2(Q2[f][0], R2l, S2l);
                A[f][1] = wgt2(Q2[f][1], R2l, S2l);
                A[f][2] = wgt2(Q2[f][0], R2h, S2h);
                A[f][3] = wgt2(Q2[f][1], R2h, S2h);
            }

            mma16(zac[0], A[0], ONES, ONES);
            mma16(zac[1], A[1], ONES, ONES);

            const uint32_t kaddr = bbase + (uint32_t)ks * (16 * BROW * 2);
#pragma unroll
            for (int pnt = 0; pnt < 4; pnt++) {
                uint32_t b0a, b1a, b0b, b1b;
                ldsm4t(b0a, b1a, b0b, b1b, kaddr + pnt * 32);
                mma16(acc[0][pnt * 2],     A[0], b0a, b1a);
                mma16(acc[1][pnt * 2],     A[1], b0a, b1a);
                mma16(acc[0][pnt * 2 + 1], A[0], b0b, b1b);
                mma16(acc[1][pnt * 2 + 1], A[1], b0b, b1b);
            }
        }

        cur++; if (cur >= 3) cur = 0;
    }

    // epilogue: diag correction + identity + elu
#pragma unroll
    for (int f = 0; f < 2; f++) {
#pragma unroll
        for (int hh = 0; hh < 2; hh++) {
            int i  = i0 + Mg * 32 + f * 16 + gid + hh * 8;
            int gi = rowbase + i;
            float Z = zac[f][hh * 2];
            __half wh = __hmax(g_Rh[gi], __hmul(g_Qh[gi], g_Sh[gi]));
            float wii = __half2float(wh);
            float inv = 1.f / (Z - wii);
            const float* hi = Hb + (size_t)i * CC;
            float* op = Out + (size_t)(b * NN + i) * CC + head * 128;
#pragma unroll
            for (int nt = 0; nt < 8; nt++) {
                int col = nbg + nt * 8 + tig * 2;
                float2 hv = *(const float2*)(hi + col);
                float v0 = (acc[f][nt][hh * 2 + 0] - wii * hv.x) * inv + hv.x;
                float v1 = (acc[f][nt][hh * 2 + 1] - wii * hv.y) * inv + hv.y;
                float2 o;
                o.x = v0 > 0.f ? v0 : expm1f(v0);
                o.y = v1 > 0.f ? v1 : expm1f(v1);
                *(float2*)(op + col) = o;
            }
        }
    }
}

// ---------------------------------------------------------------------------
extern "C" void kernel_launch(void* const* d_in, const int* in_sizes, int n_in,
                              void* d_out, int out_size)
{
    const float* x   = (const float*)d_in[0];
    const float* W00 = (const float*)d_in[2];
    const float* b00 = (const float*)d_in[3];
    const float* a00 = (const float*)d_in[4];
    const float* W01 = (const float*)d_in[5];
    const float* b01 = (const float*)d_in[6];
    const float* a01 = (const float*)d_in[7];
    const float* W10 = (const float*)d_in[8];
    const float* b10 = (const float*)d_in[9];
    const float* a10 = (const float*)d_in[10];
    const float* W11 = (const float*)d_in[11];
    const float* b11 = (const float*)d_in[12];
    const float* a11 = (const float*)d_in[13];
    float* out = (float*)d_out;

    float *H, *feat;
    cudaGetSymbolAddress((void**)&H,    g_H);
    cudaGetSymbolAddress((void**)&feat, g_feat);

    dim3 gemm_grid(MM / 128, 2);
    dim3 attn_grid(NN / 64, BB, 2);     // 32 x 8 x 2 = 512 CTAs

    wsplit_kernel<<<512, 256>>>(W00, W01, W10, W11);

    // ---- Layer 1 ----
    gemm_mma_kernel<<<gemm_grid, 256>>>(x, a00, a01, b00, b01, H, 0);
    maxpqrs_kernel<<<16, 256>>>();
    attn_mma_kernel<<<attn_grid, 128>>>(H, feat);

    // ---- Layer 2 ----
    gemm_mma_kernel<<<gemm_grid, 256>>>(feat, a10, a11, b10, b11, H, 1);
    maxpqrs_kernel<<<16, 256>>>();
    attn_mma_kernel<<<attn_grid, 128>>>(H, out);
}